// round 17
// baseline (speedup 1.0000x reference)
#include <cuda_runtime.h>
#include <cstdint>

#define NA 100000
#define NH 20000
#define NE 1000000
#define EL 200000
#define D  128

// ---------------- device scratch (static, no allocations) ----------------
__device__ int   g_cnt_a[NA];
__device__ int   g_cnt_h[NH];
__device__ int   g_ptr_a[NA + 1];
__device__ int   g_ptr_h[NH + 1];
__device__ int   g_cur_a[NA];
__device__ int   g_cur_h[NH];
__device__ int   g_csr_ah[NE];
__device__ int   g_csr_ha[NE];
__device__ float g_h_a[(size_t)NA * D];
__device__ float g_h_h[(size_t)NH * D];
__device__ float g_z_a[(size_t)NA * D];
__device__ float g_z_h[(size_t)NH * D];
// transposed + bf16 hi/lo split weights: 5 configs x {hi,lo} x [128 n][256 k] bf16
__device__ uint16_t g_wt[5][2][128 * 256];

// ---------------- PTX helpers (sm_80-compatible only; NO tcgen05) ----------------
__device__ __forceinline__ uint32_t smem_u32(const void* p) {
    uint32_t a;
    asm("{ .reg .u64 t; cvta.to.shared.u64 t, %1; cvt.u32.u64 %0, t; }" : "=r"(a) : "l"(p));
    return a;
}
__device__ __forceinline__ uint32_t pack_bf16x2(float hi_elem, float lo_elem) {
    uint32_t d;
    asm("cvt.rn.bf16x2.f32 %0, %1, %2;" : "=r"(d) : "f"(hi_elem), "f"(lo_elem));
    return d;
}
__device__ __forceinline__ float bf16_lo_as_f32(uint32_t p) { return __uint_as_float(p << 16); }
__device__ __forceinline__ float bf16_hi_as_f32(uint32_t p) { return __uint_as_float(p & 0xFFFF0000u); }

#define LDSM_X4(r, addr) \
    asm volatile("ldmatrix.sync.aligned.m8n8.x4.shared.b16 {%0,%1,%2,%3}, [%4];" \
        : "=r"((r)[0]), "=r"((r)[1]), "=r"((r)[2]), "=r"((r)[3]) : "r"(addr))

__device__ __forceinline__ void mma_bf16(float* c, const uint32_t* a, const uint32_t* b) {
    asm volatile(
        "mma.sync.aligned.m16n8k16.row.col.f32.bf16.bf16.f32 "
        "{%0,%1,%2,%3}, {%4,%5,%6,%7}, {%8,%9}, {%0,%1,%2,%3};"
        : "+f"(c[0]), "+f"(c[1]), "+f"(c[2]), "+f"(c[3])
        : "r"(a[0]), "r"(a[1]), "r"(a[2]), "r"(a[3]), "r"(b[0]), "r"(b[1]));
}

// ---------------- small utility kernels ----------------
__global__ void zero_int_kernel(int* p, int n) {
    int i = blockIdx.x * blockDim.x + threadIdx.x;
    if (i < n) p[i] = 0;
}
__global__ void hist_kernel(const int* __restrict__ dst, int* __restrict__ cnt, int n) {
    int i = blockIdx.x * blockDim.x + threadIdx.x;
    if (i < n) atomicAdd(&cnt[dst[i]], 1);
}
__global__ void scatter_kernel(const int* __restrict__ src, const int* __restrict__ dst,
                               int* __restrict__ cur, int* __restrict__ csr, int n) {
    int i = blockIdx.x * blockDim.x + threadIdx.x;
    if (i < n) {
        int d = dst[i];
        int p = atomicAdd(&cur[d], 1);
        csr[p] = src[i];
    }
}
// single-block exclusive scan; writes ptr[0..n] AND cur[0..n-1]
__global__ void exscan_kernel(const int* __restrict__ cnt, int* __restrict__ ptr,
                              int* __restrict__ cur, int n) {
    __shared__ int warp_sums[32];
    __shared__ int s_carry;
    int tid = threadIdx.x;
    int lane = tid & 31, wid = tid >> 5;
    if (tid == 0) s_carry = 0;
    __syncthreads();
    for (int base = 0; base < n; base += 1024) {
        int i = base + tid;
        int v = (i < n) ? cnt[i] : 0;
        int x = v;
        #pragma unroll
        for (int o = 1; o < 32; o <<= 1) {
            int y = __shfl_up_sync(0xFFFFFFFFu, x, o);
            if (lane >= o) x += y;
        }
        if (lane == 31) warp_sums[wid] = x;
        __syncthreads();
        if (wid == 0) {
            int s = warp_sums[lane];
            #pragma unroll
            for (int o = 1; o < 32; o <<= 1) {
                int y = __shfl_up_sync(0xFFFFFFFFu, s, o);
                if (lane >= o) s += y;
            }
            warp_sums[lane] = s;
        }
        __syncthreads();
        int incl = x + ((wid > 0) ? warp_sums[wid - 1] : 0);
        int carry = s_carry;
        if (i < n) { int e = carry + incl - v; ptr[i] = e; cur[i] = e; }
        __syncthreads();
        if (tid == 1023) s_carry = carry + incl;
        __syncthreads();
    }
    if (tid == 0) ptr[n] = s_carry;
}

// ---------------- weight transpose + bf16 hi/lo split (all 5 configs) ----------------
struct WSplitArgs {
    const float* wl[5];
    const float* wr[5];
    uint16_t* hi[5];
    uint16_t* lo[5];
};
__global__ void wsplit_all_kernel(WSplitArgs a) {
    int cfg = blockIdx.y;
    int idx = blockIdx.x * blockDim.x + threadIdx.x;
    if (idx >= 128 * 256) return;
    int n = idx >> 8;
    int k = idx & 255;
    float v = (k < 128) ? a.wl[cfg][(size_t)k * 128 + n] : a.wr[cfg][(size_t)(k - 128) * 128 + n];
    uint32_t h = pack_bf16x2(0.f, v);
    float hf = bf16_lo_as_f32(h);
    uint32_t l = pack_bf16x2(0.f, v - hf);
    a.hi[cfg][idx] = (uint16_t)(h & 0xFFFF);
    a.lo[cfg][idx] = (uint16_t)(l & 0xFFFF);
}

// ---------------- fused gather + bf16-split tensor-core GEMM ----------------
// MODE 0 (SAGE): C[M,128] = [mean-gather(Xsrc via CSR) | Xdst] @ Wt^T + bias (relu opt)
// MODE 1 (DECODER): A row m = [Xsrc[p0[m]] | Xdst[p1[m]]]; also writes A to z1out.
// CTA tile: 64 rows (M) x 128 (N), K=256 in 8 chunks of 32.
// A: K-resident smem, 8 chunks x 64 rows x 80B, hi+lo = 81920 B.
// B: single-buffered 20480 B, next chunk staged in registers (ldg) during MMA.
// Total smem 102400 -> 2 CTAs/SM: gather phase of one CTA overlaps MMA of the other.
#define ACH   5120                 // per-chunk A tile bytes (64 rows * 80)
#define ALO   40960                // A_lo offset (8 * ACH)
#define BOFF  81920                // B base
#define BLO   10240                // B_lo offset from B base
#define FSM_BYTES (102400 + 128)

__device__ __forceinline__ void stA_split(uint32_t tb, int row, int lane, int cbase, float4 v) {
    uint32_t h01 = pack_bf16x2(v.y, v.x);
    uint32_t h23 = pack_bf16x2(v.w, v.z);
    float lx = v.x - bf16_lo_as_f32(h01);
    float ly = v.y - bf16_hi_as_f32(h01);
    float lz = v.z - bf16_lo_as_f32(h23);
    float lw = v.w - bf16_hi_as_f32(h23);
    uint32_t l01 = pack_bf16x2(ly, lx);
    uint32_t l23 = pack_bf16x2(lw, lz);
    uint32_t ad = tb + (uint32_t)(cbase + (lane >> 3)) * ACH + row * 80 + (lane & 7) * 8;
    asm volatile("st.shared.v2.b32 [%0], {%1, %2};" :: "r"(ad), "r"(h01), "r"(h23) : "memory");
    asm volatile("st.shared.v2.b32 [%0], {%1, %2};" :: "r"(ad + ALO), "r"(l01), "r"(l23) : "memory");
}

template <int MODE>
__global__ void __launch_bounds__(256, 2)
fused_gemm_kernel(const float* __restrict__ Xsrc, const float* __restrict__ Xdst,
                  const int* __restrict__ p0, const int* __restrict__ p1,
                  const uint16_t* __restrict__ Whi, const uint16_t* __restrict__ Wlo,
                  const float* __restrict__ bias,
                  float* __restrict__ C, float* __restrict__ z1out,
                  int M, int relu) {
    extern __shared__ char smem[];
    uint32_t tb = (smem_u32(smem) + 127) & ~127u;

    int tid = threadIdx.x;
    int wid = tid >> 5, lane = tid & 31;
    int warpM = wid >> 2;        // 0..1 (32-row halves)
    int warpN = wid & 3;         // 0..3 (32-col groups)
    int row0 = blockIdx.x * 64;

    // ---- prefetch B chunk 0 (completes during the gather phase) ----
    #pragma unroll
    for (int i = 0; i < 2; i++) {
        int p = tid + i * 256;
        int r = p >> 2, q = p & 3;
        size_t g = (size_t)r * 256 + q * 8;
        uint32_t dsm = tb + BOFF + r * 80 + q * 16;
        asm volatile("cp.async.cg.shared.global [%0], [%1], 16;" :: "r"(dsm), "l"(Whi + g) : "memory");
        asm volatile("cp.async.cg.shared.global [%0], [%1], 16;" :: "r"(dsm + BLO), "l"(Wlo + g) : "memory");
    }
    asm volatile("cp.async.commit_group;" ::: "memory");

    // ---- phase 1: build A tile in smem (bf16 hi/lo split, K-resident) ----
    #pragma unroll 1
    for (int r8 = 0; r8 < 8; r8++) {
        int row = wid * 8 + r8;
        int grow = row0 + row;
        if (grow >= M) break;
        if (MODE == 0) {
            int s = p0[grow], e = p0[grow + 1];
            float ax = 0.f, ay = 0.f, az = 0.f, aw = 0.f;
            float bx = 0.f, by = 0.f, bz = 0.f, bw = 0.f;
            int i = s;
            for (; i + 4 <= e; i += 4) {
                int s0 = __ldg(&p1[i]);
                int s1 = __ldg(&p1[i + 1]);
                int s2 = __ldg(&p1[i + 2]);
                int s3 = __ldg(&p1[i + 3]);
                float4 v0 = *reinterpret_cast<const float4*>(Xsrc + (size_t)s0 * D + lane * 4);
                float4 v1 = *reinterpret_cast<const float4*>(Xsrc + (size_t)s1 * D + lane * 4);
                float4 v2 = *reinterpret_cast<const float4*>(Xsrc + (size_t)s2 * D + lane * 4);
                float4 v3 = *reinterpret_cast<const float4*>(Xsrc + (size_t)s3 * D + lane * 4);
                ax += v0.x; ay += v0.y; az += v0.z; aw += v0.w;
                bx += v1.x; by += v1.y; bz += v1.z; bw += v1.w;
                ax += v2.x; ay += v2.y; az += v2.z; aw += v2.w;
                bx += v3.x; by += v3.y; bz += v3.z; bw += v3.w;
            }
            for (; i < e; i++) {
                int s0 = __ldg(&p1[i]);
                float4 v0 = *reinterpret_cast<const float4*>(Xsrc + (size_t)s0 * D + lane * 4);
                ax += v0.x; ay += v0.y; az += v0.z; aw += v0.w;
            }
            ax += bx; ay += by; az += bz; aw += bw;
            int deg = e - s;
            float inv = 1.0f / (float)(deg > 0 ? deg : 1);
            stA_split(tb, row, lane, 0, make_float4(ax * inv, ay * inv, az * inv, aw * inv));
            float4 vd = *reinterpret_cast<const float4*>(Xdst + (size_t)grow * D + lane * 4);
            stA_split(tb, row, lane, 4, vd);
        } else {
            int r = __ldg(&p0[grow]);
            int c = __ldg(&p1[grow]);
            float4 va = *reinterpret_cast<const float4*>(Xsrc + (size_t)r * D + lane * 4);
            float4 vb = *reinterpret_cast<const float4*>(Xdst + (size_t)c * D + lane * 4);
            *reinterpret_cast<float4*>(z1out + (size_t)grow * 256 + lane * 4)       = va;
            *reinterpret_cast<float4*>(z1out + (size_t)grow * 256 + 128 + lane * 4) = vb;
            stA_split(tb, row, lane, 0, va);
            stA_split(tb, row, lane, 4, vb);
        }
    }

    asm volatile("cp.async.wait_group 0;" ::: "memory");
    __syncthreads();

    // ---- phase 2: GEMM over 8 K-chunks; B next-chunk register staging ----
    float acc[2][4][4];
    #pragma unroll
    for (int mt = 0; mt < 2; mt++)
        #pragma unroll
        for (int nt = 0; nt < 4; nt++)
            #pragma unroll
            for (int j = 0; j < 4; j++) acc[mt][nt][j] = 0.f;

    uint4 rBh[2], rBl[2];

    #pragma unroll 1
    for (int kc = 0; kc < 8; ++kc) {
        if (kc < 7) {
            #pragma unroll
            for (int i = 0; i < 2; i++) {
                int p = tid + i * 256;
                int r = p >> 2, q = p & 3;
                size_t g = (size_t)r * 256 + (kc + 1) * 32 + q * 8;
                rBh[i] = *reinterpret_cast<const uint4*>(Whi + g);
                rBl[i] = *reinterpret_cast<const uint4*>(Wlo + g);
            }
        }

        uint32_t aBase = tb + kc * ACH;
        uint32_t bBase = tb + BOFF;
        #pragma unroll
        for (int ks = 0; ks < 2; ks++) {
            uint32_t Bh[4][2], Bl[4][2];
            #pragma unroll
            for (int ng = 0; ng < 2; ng++) {
                uint32_t ad = bBase + (warpN * 32 + ng * 16 + (lane & 15)) * 80
                            + ks * 32 + (lane >> 4) * 16;
                uint32_t r[4];
                LDSM_X4(r, ad);
                Bh[ng * 2][0] = r[0]; Bh[ng * 2][1] = r[2];
                Bh[ng * 2 + 1][0] = r[1]; Bh[ng * 2 + 1][1] = r[3];
                LDSM_X4(r, ad + BLO);
                Bl[ng * 2][0] = r[0]; Bl[ng * 2][1] = r[2];
                Bl[ng * 2 + 1][0] = r[1]; Bl[ng * 2 + 1][1] = r[3];
            }
            #pragma unroll
            for (int mt = 0; mt < 2; mt++) {
                uint32_t ad = aBase + (warpM * 32 + mt * 16 + (lane & 15)) * 80
                            + ks * 32 + (lane >> 4) * 16;
                uint32_t Ah[4];
                LDSM_X4(Ah, ad);
                #pragma unroll
                for (int nt = 0; nt < 4; nt++) mma_bf16(acc[mt][nt], Ah, Bh[nt]); // hi*hi
                #pragma unroll
                for (int nt = 0; nt < 4; nt++) mma_bf16(acc[mt][nt], Ah, Bl[nt]); // hi*lo
                uint32_t Al[4];
                LDSM_X4(Al, ad + ALO);
                #pragma unroll
                for (int nt = 0; nt < 4; nt++) mma_bf16(acc[mt][nt], Al, Bh[nt]); // lo*hi
            }
        }

        __syncthreads();
        if (kc < 7) {
            #pragma unroll
            for (int i = 0; i < 2; i++) {
                int p = tid + i * 256;
                int r = p >> 2, q = p & 3;
                uint32_t ad = tb + BOFF + r * 80 + q * 16;
                asm volatile("st.shared.v4.b32 [%0], {%1, %2, %3, %4};"
                    :: "r"(ad), "r"(rBh[i].x), "r"(rBh[i].y), "r"(rBh[i].z), "r"(rBh[i].w) : "memory");
                asm volatile("st.shared.v4.b32 [%0], {%1, %2, %3, %4};"
                    :: "r"(ad + BLO), "r"(rBl[i].x), "r"(rBl[i].y), "r"(rBl[i].z), "r"(rBl[i].w) : "memory");
            }
            __syncthreads();
        }
    }

    // ---- epilogue ----
    #pragma unroll
    for (int mt = 0; mt < 2; mt++) {
        int rg = row0 + warpM * 32 + mt * 16 + (lane >> 2);
        #pragma unroll
        for (int nt = 0; nt < 4; nt++) {
            int col = warpN * 32 + nt * 8 + ((lane & 3) << 1);
            float2 bv = *reinterpret_cast<const float2*>(bias + col);
            float2 o0, o1;
            o0.x = acc[mt][nt][0] + bv.x; o0.y = acc[mt][nt][1] + bv.y;
            o1.x = acc[mt][nt][2] + bv.x; o1.y = acc[mt][nt][3] + bv.y;
            if (relu) {
                o0.x = fmaxf(o0.x, 0.f); o0.y = fmaxf(o0.y, 0.f);
                o1.x = fmaxf(o1.x, 0.f); o1.y = fmaxf(o1.y, 0.f);
            }
            if (rg < M)     *reinterpret_cast<float2*>(C + (size_t)rg * D + col) = o0;
            if (rg + 8 < M) *reinterpret_cast<float2*>(C + (size_t)(rg + 8) * D + col) = o1;
        }
    }
}

// ---------------- pred = z2 @ W_lin2 + b_lin2 (one warp per row) ----------------
__global__ void pred_kernel(const float* __restrict__ z2, const float* __restrict__ w2,
                            const float* __restrict__ b2, float* __restrict__ out, int n) {
    int w = (blockIdx.x * blockDim.x + threadIdx.x) >> 5;
    int lane = threadIdx.x & 31;
    if (w >= n) return;
    float4 v  = *reinterpret_cast<const float4*>(z2 + (size_t)w * D + lane * 4);
    float4 ww = *reinterpret_cast<const float4*>(w2 + lane * 4);
    float s = v.x * ww.x + v.y * ww.y + v.z * ww.z + v.w * ww.w;
    #pragma unroll
    for (int o = 16; o > 0; o >>= 1) s += __shfl_xor_sync(0xFFFFFFFFu, s, o);
    if (lane == 0) out[w] = s + b2[0];
}

// ---------------- host launch ----------------
static inline int divup(int a, int b) { return (a + b - 1) / b; }

extern "C" void kernel_launch(void* const* d_in, const int* in_sizes, int n_in,
                              void* d_out, int out_size) {
    const float* x_a    = (const float*)d_in[0];
    const float* x_h    = (const float*)d_in[1];
    const int*   ah_src = (const int*)d_in[2];
    const int*   ah_dst = (const int*)d_in[3];
    const int*   ha_src = (const int*)d_in[4];
    const int*   ha_dst = (const int*)d_in[5];
    const int*   e_row  = (const int*)d_in[6];
    const int*   e_col  = (const int*)d_in[7];

    bool sig = (in_sizes[9] == 128);
    const float *W1_ah_l, *W1_ah_r, *W1_ha_l, *W1_ha_r;
    const float *W2_ah_l, *W2_ah_r, *W2_ha_l, *W2_ha_r;
    const float *b1_ah, *b1_ha, *b2_ah, *b2_ha;
    if (sig) {
        W1_ah_l = (const float*)d_in[8];  b1_ah = (const float*)d_in[9];
        W1_ah_r = (const float*)d_in[10];
        W1_ha_l = (const float*)d_in[11]; b1_ha = (const float*)d_in[12];
        W1_ha_r = (const float*)d_in[13];
        W2_ah_l = (const float*)d_in[14]; b2_ah = (const float*)d_in[15];
        W2_ah_r = (const float*)d_in[16];
        W2_ha_l = (const float*)d_in[17]; b2_ha = (const float*)d_in[18];
        W2_ha_r = (const float*)d_in[19];
    } else {
        W1_ah_l = (const float*)d_in[8];  W1_ah_r = (const float*)d_in[9];
        W1_ha_l = (const float*)d_in[10]; W1_ha_r = (const float*)d_in[11];
        W2_ah_l = (const float*)d_in[12]; W2_ah_r = (const float*)d_in[13];
        W2_ha_l = (const float*)d_in[14]; W2_ha_r = (const float*)d_in[15];
        b1_ah = (const float*)d_in[16];   b1_ha = (const float*)d_in[17];
        b2_ah = (const float*)d_in[18];   b2_ha = (const float*)d_in[19];
    }
    const float* W_lin1 = (const float*)d_in[20];
    const float* b_lin1 = (const float*)d_in[21];
    const float* W_lin2 = (const float*)d_in[22];
    const float* b_lin2 = (const float*)d_in[23];

    float* out  = (float*)d_out;
    float* pred = out;
    float* z1   = out + EL;
    float* z2   = out + EL + (size_t)EL * 256;

    int *cnt_a, *cnt_h, *ptr_a, *ptr_h, *cur_a, *cur_h, *csr_ah, *csr_ha;
    float *h_a, *h_h, *z_a, *z_h;
    uint16_t* wt;
    cudaGetSymbolAddress((void**)&cnt_a, g_cnt_a);
    cudaGetSymbolAddress((void**)&cnt_h, g_cnt_h);
    cudaGetSymbolAddress((void**)&ptr_a, g_ptr_a);
    cudaGetSymbolAddress((void**)&ptr_h, g_ptr_h);
    cudaGetSymbolAddress((void**)&cur_a, g_cur_a);
    cudaGetSymbolAddress((void**)&cur_h, g_cur_h);
    cudaGetSymbolAddress((void**)&csr_ah, g_csr_ah);
    cudaGetSymbolAddress((void**)&csr_ha, g_csr_ha);
    cudaGetSymbolAddress((void**)&h_a, g_h_a);
    cudaGetSymbolAddress((void**)&h_h, g_h_h);
    cudaGetSymbolAddress((void**)&z_a, g_z_a);
    cudaGetSymbolAddress((void**)&z_h, g_z_h);
    cudaGetSymbolAddress((void**)&wt, g_wt);

    const int WSZ = 128 * 256;
    uint16_t* wt_hi[5]; uint16_t* wt_lo[5];
    for (int i = 0; i < 5; i++) { wt_hi[i] = wt + (size_t)i * 2 * WSZ; wt_lo[i] = wt_hi[i] + WSZ; }

    cudaFuncSetAttribute(fused_gemm_kernel<0>, cudaFuncAttributeMaxDynamicSharedMemorySize, FSM_BYTES);
    cudaFuncSetAttribute(fused_gemm_kernel<1>, cudaFuncAttributeMaxDynamicSharedMemorySize, FSM_BYTES);

    const int TB = 256;

    // ---- weight transpose + split (single launch, all 5 configs) ----
    WSplitArgs wa;
    wa.wl[0] = W1_ah_l; wa.wr[0] = W1_ah_r;
    wa.wl[1] = W1_ha_l; wa.wr[1] = W1_ha_r;
    wa.wl[2] = W2_ah_l; wa.wr[2] = W2_ah_r;
    wa.wl[3] = W2_ha_l; wa.wr[3] = W2_ha_r;
    wa.wl[4] = W_lin1;  wa.wr[4] = W_lin1 + 128 * 128;
    for (int i = 0; i < 5; i++) { wa.hi[i] = wt_hi[i]; wa.lo[i] = wt_lo[i]; }
    {
        dim3 grid(divup(WSZ, TB), 5);
        wsplit_all_kernel<<<grid, TB>>>(wa);
    }

    // ---- CSR build: a->h edges grouped by hotel dst ----
    zero_int_kernel<<<divup(NH, TB), TB>>>(cnt_h, NH);
    hist_kernel<<<divup(NE, TB), TB>>>(ah_dst, cnt_h, NE);
    exscan_kernel<<<1, 1024>>>(cnt_h, ptr_h, cur_h, NH);
    scatter_kernel<<<divup(NE, TB), TB>>>(ah_src, ah_dst, cur_h, csr_ah, NE);

    // ---- CSR build: h->a edges grouped by author dst ----
    zero_int_kernel<<<divup(NA, TB), TB>>>(cnt_a, NA);
    hist_kernel<<<divup(NE, TB), TB>>>(ha_dst, cnt_a, NE);
    exscan_kernel<<<1, 1024>>>(cnt_a, ptr_a, cur_a, NA);
    scatter_kernel<<<divup(NE, TB), TB>>>(ha_src, ha_dst, cur_a, csr_ha, NE);

    // ---- Layer 1 (fused gather-mean + GEMM) ----
    fused_gemm_kernel<0><<<divup(NH, 64), TB, FSM_BYTES>>>(
        x_a, x_h, ptr_h, csr_ah, wt_hi[0], wt_lo[0], b1_ah, h_h, nullptr, NH, 1);
    fused_gemm_kernel<0><<<divup(NA, 64), TB, FSM_BYTES>>>(
        x_h, x_a, ptr_a, csr_ha, wt_hi[1], wt_lo[1], b1_ha, h_a, nullptr, NA, 1);

    // ---- Layer 2 ----
    fused_gemm_kernel<0><<<divup(NH, 64), TB, FSM_BYTES>>>(
        h_a, h_h, ptr_h, csr_ah, wt_hi[2], wt_lo[2], b2_ah, z_h, nullptr, NH, 0);
    fused_gemm_kernel<0><<<divup(NA, 64), TB, FSM_BYTES>>>(
        h_h, h_a, ptr_a, csr_ha, wt_hi[3], wt_lo[3], b2_ha, z_a, nullptr, NA, 0);

    // ---- Decoder (fused gather-concat + GEMM; also emits z1) ----
    fused_gemm_kernel<1><<<divup(EL, 64), TB, FSM_BYTES>>>(
        z_a, z_h, e_row, e_col, wt_hi[4], wt_lo[4], b_lin1, z2, z1, EL, 1);
    pred_kernel<<<divup(EL * 32, TB), TB>>>(z2, W_lin2, b_lin2, pred, EL);
}